// round 1
// baseline (speedup 1.0000x reference)
#include <cuda_runtime.h>

// Problem: weighted MSE over predict/target of shape [64, 3, 17, 4096] fp32.
//   w = {1, 1, 75825} per channel (dim 1), result = sum(w * (t-p)^2) / (64*17*4096)
//
// N elements  = 64*3*17*4096 = 13,369,344
// N float4    = 3,342,336 = 1632 blocks * 256 threads * 8 vecs
// Channel of element i = (i / (17*4096)) % 3 ; 17*4096 = 69632 divisible by 4,
// so per-float4 channel = (v / 17408) % 3.

#define NVEC        3342336
#define VEC_PER_CH  17408        // 17*4096/4
#define NBLOCKS     1632
#define NTHREADS    256
#define VPT         8            // vecs per thread
#define MAXLEN_W    75825.0f
#define INV_DENOM   (1.0f / 4456448.0f)   // 1/(64*17*4096)

__device__ float g_partials[NBLOCKS];

__global__ __launch_bounds__(NTHREADS) void mse_partial_kernel(
    const float4* __restrict__ predict,
    const float4* __restrict__ target)
{
    const int tid = blockIdx.x * NTHREADS + threadIdx.x;

    float s = 0.0f;
#pragma unroll
    for (int j = 0; j < VPT; j++) {
        const int v = tid + j * (NBLOCKS * NTHREADS);   // coalesced, v < NVEC exactly
        const float4 a = predict[v];
        const float4 b = target[v];
        const int ch = (v / VEC_PER_CH) % 3;
        const float w = (ch == 2) ? MAXLEN_W : 1.0f;
        const float d0 = b.x - a.x;
        const float d1 = b.y - a.y;
        const float d2 = b.z - a.z;
        const float d3 = b.w - a.w;
        s += w * (d0 * d0 + d1 * d1 + d2 * d2 + d3 * d3);
    }

    // warp reduce
#pragma unroll
    for (int off = 16; off > 0; off >>= 1)
        s += __shfl_down_sync(0xFFFFFFFFu, s, off);

    __shared__ float smem[NTHREADS / 32];
    const int lane = threadIdx.x & 31;
    const int wid  = threadIdx.x >> 5;
    if (lane == 0) smem[wid] = s;
    __syncthreads();

    if (wid == 0) {
        s = (lane < NTHREADS / 32) ? smem[lane] : 0.0f;
#pragma unroll
        for (int off = 4; off > 0; off >>= 1)
            s += __shfl_down_sync(0xFFFFFFFFu, s, off);
        if (lane == 0) g_partials[blockIdx.x] = s;
    }
}

__global__ __launch_bounds__(512) void mse_final_kernel(float* __restrict__ out)
{
    float s = 0.0f;
    for (int i = threadIdx.x; i < NBLOCKS; i += 512)
        s += g_partials[i];

#pragma unroll
    for (int off = 16; off > 0; off >>= 1)
        s += __shfl_down_sync(0xFFFFFFFFu, s, off);

    __shared__ float smem[16];
    const int lane = threadIdx.x & 31;
    const int wid  = threadIdx.x >> 5;
    if (lane == 0) smem[wid] = s;
    __syncthreads();

    if (wid == 0) {
        s = (lane < 16) ? smem[lane] : 0.0f;
#pragma unroll
        for (int off = 8; off > 0; off >>= 1)
            s += __shfl_down_sync(0xFFFFFFFFu, s, off);
        if (lane == 0) out[0] = s * INV_DENOM;
    }
}

extern "C" void kernel_launch(void* const* d_in, const int* in_sizes, int n_in,
                              void* d_out, int out_size)
{
    const float4* predict = (const float4*)d_in[0];
    const float4* target  = (const float4*)d_in[1];
    float* out = (float*)d_out;

    mse_partial_kernel<<<NBLOCKS, NTHREADS>>>(predict, target);
    mse_final_kernel<<<1, 512>>>(out);
}

// round 2
// speedup vs baseline: 1.0207x; 1.0207x over previous
#include <cuda_runtime.h>

// Weighted MSE over predict/target [64, 3, 17, 4096] fp32.
//   w = {1, 1, 75825} per channel (dim 1), result = sum(w*(t-p)^2) / (64*17*4096)
//
// N elements = 13,369,344 ; N float4 = 3,342,336 = 2^16 * 51
// Channel of float4 v = (v / 17408) % 3   (17408 = 17*4096/4)
//
// Single-wave grid: 148 SMs * 8 CTAs = 1184 blocks * 256 thr = 303,104 threads.
// 11 vecs/thread fixed (3,334,144) + 8,192 remainder vecs on the first threads.
// Single kernel: last-block-done pattern fuses the final reduction (kills the
// ~5.7us second launch seen in R1). Counter self-resets => graph-replay safe.

#define NVEC        3342336
#define VEC_PER_CH  17408
#define NBLOCKS     1184
#define NTHREADS    256
#define STRIDE      (NBLOCKS * NTHREADS)      // 303104
#define VPT         11                        // 11*STRIDE = 3334144
#define REM         (NVEC - VPT * STRIDE)     // 8192
#define MAXLEN_W    75825.0f
#define INV_DENOM   (1.0f / 4456448.0f)       // 1/(64*17*4096)

__device__ float g_partials[NBLOCKS];
__device__ unsigned int g_count;              // zero-init; last block resets it

__device__ __forceinline__ float vec_term(const float4 a, const float4 b, const int v)
{
    const int ch = (v / VEC_PER_CH) % 3;
    const float w = (ch == 2) ? MAXLEN_W : 1.0f;
    const float d0 = b.x - a.x;
    const float d1 = b.y - a.y;
    const float d2 = b.z - a.z;
    const float d3 = b.w - a.w;
    return w * (d0 * d0 + d1 * d1 + d2 * d2 + d3 * d3);
}

__global__ __launch_bounds__(NTHREADS) void mse_fused_kernel(
    const float4* __restrict__ predict,
    const float4* __restrict__ target,
    float* __restrict__ out)
{
    const int tid = blockIdx.x * NTHREADS + threadIdx.x;

    float s = 0.0f;
#pragma unroll
    for (int j = 0; j < VPT; j++) {
        const int v = tid + j * STRIDE;
        s += vec_term(predict[v], target[v], v);
    }
    if (tid < REM) {
        const int v = tid + VPT * STRIDE;
        s += vec_term(predict[v], target[v], v);
    }

    // block reduce
#pragma unroll
    for (int off = 16; off > 0; off >>= 1)
        s += __shfl_down_sync(0xFFFFFFFFu, s, off);

    __shared__ float smem[NTHREADS / 32];
    const int lane = threadIdx.x & 31;
    const int wid  = threadIdx.x >> 5;
    if (lane == 0) smem[wid] = s;
    __syncthreads();

    __shared__ bool is_last;
    if (threadIdx.x == 0) {
        float bs = 0.0f;
#pragma unroll
        for (int i = 0; i < NTHREADS / 32; i++) bs += smem[i];
        g_partials[blockIdx.x] = bs;
        __threadfence();
        const unsigned int old = atomicAdd(&g_count, 1u);
        is_last = (old == NBLOCKS - 1);
    }
    __syncthreads();

    if (is_last) {
        // last arriving block: all partials are globally visible now
        float t = 0.0f;
        for (int i = threadIdx.x; i < NBLOCKS; i += NTHREADS)
            t += g_partials[i];

#pragma unroll
        for (int off = 16; off > 0; off >>= 1)
            t += __shfl_down_sync(0xFFFFFFFFu, t, off);

        if (lane == 0) smem[wid] = t;
        __syncthreads();

        if (threadIdx.x == 0) {
            float r = 0.0f;
#pragma unroll
            for (int i = 0; i < NTHREADS / 32; i++) r += smem[i];
            out[0] = r * INV_DENOM;
            g_count = 0;   // reset for next graph replay
        }
    }
}

extern "C" void kernel_launch(void* const* d_in, const int* in_sizes, int n_in,
                              void* d_out, int out_size)
{
    const float4* predict = (const float4*)d_in[0];
    const float4* target  = (const float4*)d_in[1];
    float* out = (float*)d_out;

    mse_fused_kernel<<<NBLOCKS, NTHREADS>>>(predict, target, out);
}

// round 3
// speedup vs baseline: 1.1212x; 1.0985x over previous
#include <cuda_runtime.h>

// Weighted MSE over predict/target [64, 3, 17, 4096] fp32.
//   w = {1, 1, 75825} per channel (dim 1), result = sum(w*(t-p)^2) / (64*17*4096)
//
// N float4 = 3,342,336 ; channel of float4 v = (v / 17408) % 3
//
// R3 change: __launch_bounds__(256, 8) forces <=32 regs so 8 CTAs/SM fit and
// the 1184-block grid is EXACTLY one wave (R2 compiled to 40 regs -> 6 CTAs/SM
// -> 1.33 waves -> DRAM stuck at 59.6%).

#define NVEC        3342336
#define VEC_PER_CH  17408
#define NBLOCKS     1184
#define NTHREADS    256
#define STRIDE      (NBLOCKS * NTHREADS)      // 303104
#define VPT         11                        // 11*STRIDE = 3334144
#define REM         (NVEC - VPT * STRIDE)     // 8192
#define MAXLEN_W    75825.0f
#define INV_DENOM   (1.0f / 4456448.0f)       // 1/(64*17*4096)

__device__ float g_partials[NBLOCKS];
__device__ unsigned int g_count;              // zero-init; last block resets it

__device__ __forceinline__ float vec_term(const float4 a, const float4 b, const int v)
{
    const int ch = (v / VEC_PER_CH) % 3;
    const float w = (ch == 2) ? MAXLEN_W : 1.0f;
    const float d0 = b.x - a.x;
    const float d1 = b.y - a.y;
    const float d2 = b.z - a.z;
    const float d3 = b.w - a.w;
    return w * (d0 * d0 + d1 * d1 + d2 * d2 + d3 * d3);
}

__global__ __launch_bounds__(NTHREADS, 8) void mse_fused_kernel(
    const float4* __restrict__ predict,
    const float4* __restrict__ target,
    float* __restrict__ out)
{
    const int tid = blockIdx.x * NTHREADS + threadIdx.x;

    float s = 0.0f;
#pragma unroll
    for (int j = 0; j < VPT; j++) {
        const int v = tid + j * STRIDE;
        s += vec_term(predict[v], target[v], v);
    }
    if (tid < REM) {
        const int v = tid + VPT * STRIDE;
        s += vec_term(predict[v], target[v], v);
    }

    // block reduce
#pragma unroll
    for (int off = 16; off > 0; off >>= 1)
        s += __shfl_down_sync(0xFFFFFFFFu, s, off);

    __shared__ float smem[NTHREADS / 32];
    const int lane = threadIdx.x & 31;
    const int wid  = threadIdx.x >> 5;
    if (lane == 0) smem[wid] = s;
    __syncthreads();

    __shared__ bool is_last;
    if (threadIdx.x == 0) {
        float bs = 0.0f;
#pragma unroll
        for (int i = 0; i < NTHREADS / 32; i++) bs += smem[i];
        g_partials[blockIdx.x] = bs;
        __threadfence();
        const unsigned int old = atomicAdd(&g_count, 1u);
        is_last = (old == NBLOCKS - 1);
    }
    __syncthreads();

    if (is_last) {
        // last arriving block: all partials are globally visible now
        float t = 0.0f;
        for (int i = threadIdx.x; i < NBLOCKS; i += NTHREADS)
            t += g_partials[i];

#pragma unroll
        for (int off = 16; off > 0; off >>= 1)
            t += __shfl_down_sync(0xFFFFFFFFu, t, off);

        if (lane == 0) smem[wid] = t;
        __syncthreads();

        if (threadIdx.x == 0) {
            float r = 0.0f;
#pragma unroll
            for (int i = 0; i < NTHREADS / 32; i++) r += smem[i];
            out[0] = r * INV_DENOM;
            g_count = 0;   // reset for next graph replay
        }
    }
}

extern "C" void kernel_launch(void* const* d_in, const int* in_sizes, int n_in,
                              void* d_out, int out_size)
{
    const float4* predict = (const float4*)d_in[0];
    const float4* target  = (const float4*)d_in[1];
    float* out = (float*)d_out;

    mse_fused_kernel<<<NBLOCKS, NTHREADS>>>(predict, target, out);
}